// round 2
// baseline (speedup 1.0000x reference)
#include <cuda_runtime.h>
#include <math.h>

// Problem constants (fixed shapes)
#define NB 4
#define HB 512
#define WB 512
#define KB 4
#define CB 3
#define NPIX (NB * HB * WB)   // 1,048,576 pixels

#define SIGMA_F 1e-4f
#define GAMMA_F 1e-4f
// DELTA = exp(1e-10/1e-4)*1e-10 computed in float64 -> float32
#define DELTA_F 1.0000010000005e-10f

// Accumulator: per (n, y, x) -> {sum r*w, sum g*w, sum b*w, sum w}
// 4*512*512 float4 = 16 MB static device scratch.
__device__ float4 g_accum[NB * HB * WB];

__global__ void zero_accum_kernel() {
    int i = blockIdx.x * blockDim.x + threadIdx.x;
    if (i < NPIX) g_accum[i] = make_float4(0.f, 0.f, 0.f, 0.f);
}

__global__ __launch_bounds__(256) void splat_kernel(
    const int*   __restrict__ p2f,     // [N,H,W,K]
    const float* __restrict__ bary,    // [N,H,W,K,3]
    const float* __restrict__ dists,   // [N,H,W,K]
    const float* __restrict__ zbuf,    // [N,H,W,K]
    const float* __restrict__ images,  // [N,H,W,C]
    const float* __restrict__ fuv)     // [F,3,2]
{
    int idx = blockIdx.x * blockDim.x + threadIdx.x;
    if (idx >= NPIX) return;
    int w = idx % WB;
    int h = (idx / WB) % HB;
    int n = idx / (WB * HB);

    // Vectorized loads (K=4 innermost, 16B aligned)
    int4   f4 = __ldg(((const int4*)p2f) + idx);
    float4 d4 = __ldg(((const float4*)dists) + idx);
    float4 z4 = __ldg(((const float4*)zbuf) + idx);

    int   fk[4] = {f4.x, f4.y, f4.z, f4.w};
    float dk[4] = {d4.x, d4.y, d4.z, d4.w};
    float zk[4] = {z4.x, z4.y, z4.z, z4.w};

    // z_inv = (ZFAR - zbuf)/(ZFAR - ZNEAR) * mask : TRUE division (rounding
    // here is amplified x1e4 by the exp((dz)/GAMMA) below — must match ref).
    float zinv[4];
    float zmax = -1e30f;
    #pragma unroll
    for (int k = 0; k < 4; k++) {
        zinv[k] = (fk[k] >= 0) ? __fdiv_rn(__fsub_rn(100.0f, zk[k]), 99.0f) : 0.0f;
        zmax = fmaxf(zmax, zinv[k]);
    }

    // wnum = sigmoid(-d/SIGMA)*mask * exp((z_inv - z_max)/GAMMA)
    float wnum[4];
    float s = 0.0f;
    #pragma unroll
    for (int k = 0; k < 4; k++) {
        float prob = 0.0f;
        if (fk[k] >= 0) {
            float sarg = __fdiv_rn(-dk[k], SIGMA_F);           // -d/SIGMA
            prob = __fdiv_rn(1.0f, __fadd_rn(1.0f, expf(-sarg)));
        }
        float earg = __fdiv_rn(__fsub_rn(zinv[k], zmax), GAMMA_F);
        wnum[k] = __fmul_rn(prob, expf(earg));
        s = __fadd_rn(s, wnum[k]);
    }
    float denom = __fadd_rn(s, DELTA_F);

    // Pixel RGB
    float r = __ldg(images + (size_t)idx * 3 + 0);
    float g = __ldg(images + (size_t)idx * 3 + 1);
    float b = __ldg(images + (size_t)idx * 3 + 2);

    // Barycentrics: 12 contiguous floats -> 3x float4
    const float4* bq = ((const float4*)bary) + (size_t)idx * 3;
    float4 q0 = __ldg(bq + 0);
    float4 q1 = __ldg(bq + 1);
    float4 q2 = __ldg(bq + 2);
    float bc[12] = {q0.x, q0.y, q0.z, q0.w, q1.x, q1.y, q1.z, q1.w,
                    q2.x, q2.y, q2.z, q2.w};

    // linspace(0, 512, 512)[i] = i * (512/511)  (step rounded once, as JAX)
    const float STEP = 512.0f / 511.0f;
    float linx = __fmul_rn((float)w, STEP);
    float liny = __fmul_rn((float)h, STEP);

    float4* accum_n = g_accum + (size_t)n * HB * WB;

    #pragma unroll
    for (int k = 0; k < 4; k++) {
        // Exact-zero weight -> scatter of zeros -> bitwise no-op. Skip.
        if (wnum[k] == 0.0f) continue;
        float wt = __fdiv_rn(wnum[k], denom);

        // Gather face UVs (6 floats) and barycentric-blend.
        // Strict mul/add (no FMA contraction) to match XLA elementwise ops:
        // bin assignment (floor) is sensitive to last-ulp drift here.
        const float* uvp = fuv + (size_t)fk[k] * 6;
        float b0 = bc[k * 3 + 0], b1 = bc[k * 3 + 1], b2 = bc[k * 3 + 2];
        float ux = __fadd_rn(__fadd_rn(__fmul_rn(b0, __ldg(uvp + 0)),
                                       __fmul_rn(b1, __ldg(uvp + 2))),
                             __fmul_rn(b2, __ldg(uvp + 4)));
        float uy = __fadd_rn(__fadd_rn(__fmul_rn(b0, __ldg(uvp + 1)),
                                       __fmul_rn(b1, __ldg(uvp + 3))),
                             __fmul_rn(b2, __ldg(uvp + 5)));

        // grid = uv*2-1 ; target = (grid/2 + 0.5) * 512  (exact fp order, no FMA)
        float gx = __fadd_rn(__fmul_rn(ux, 2.0f), -1.0f);
        float gy = __fadd_rn(__fmul_rn(uy, 2.0f), -1.0f);
        float tgx = __fmul_rn(__fadd_rn(__fmul_rn(gx, 0.5f), 0.5f), 512.0f);
        float tgy = __fmul_rn(__fadd_rn(__fmul_rn(gy, 0.5f), 0.5f), 512.0f);

        // fx = (target - linspace) + coord   (as in _splat_one)
        float fx = __fadd_rn(__fsub_rn(tgx, linx), (float)w);
        float fy = __fadd_rn(__fsub_rn(tgy, liny), (float)h);

        float x0f = floorf(fx), y0f = floorf(fy);
        int x0 = (int)x0f, y0 = (int)y0f;
        float tx = __fsub_rn(fx, x0f), ty = __fsub_rn(fy, y0f);

        float vr = __fmul_rn(r, wt), vg = __fmul_rn(g, wt), vb = __fmul_rn(b, wt);

        #pragma unroll
        for (int dy = 0; dy < 2; dy++) {
            #pragma unroll
            for (int dx = 0; dx < 2; dx++) {
                int xi = x0 + dx;
                int yi = y0 + dy;
                if ((unsigned)xi < (unsigned)WB && (unsigned)yi < (unsigned)HB) {
                    float wx = dx ? tx : __fsub_rn(1.0f, tx);
                    float wy = dy ? ty : __fsub_rn(1.0f, ty);
                    float wgt = __fmul_rn(wx, wy);
                    float4* p = accum_n + (size_t)yi * WB + xi;
                    asm volatile(
                        "red.global.add.v4.f32 [%0], {%1, %2, %3, %4};"
                        :: "l"(p), "f"(__fmul_rn(vr, wgt)), "f"(__fmul_rn(vg, wgt)),
                           "f"(__fmul_rn(vb, wgt)), "f"(__fmul_rn(wt, wgt))
                        : "memory");
                }
            }
        }
    }
}

__global__ __launch_bounds__(256) void finalize_kernel(float* __restrict__ out) {
    int idx = blockIdx.x * blockDim.x + threadIdx.x;
    if (idx >= NPIX) return;
    int w = idx % WB;
    int h = (idx / WB) % HB;
    int n = idx / (WB * HB);

    // Flip H: output row h reads accumulator row (H-1-h)
    float4 a = g_accum[((size_t)n * HB + (HB - 1 - h)) * WB + w];
    float wsum = a.w;
    float c = fmaxf(wsum, 1e-8f);   // jnp.clip(wsum, 1e-8) lower bound

    float* tex = out + (size_t)idx * 3;
    tex[0] = __fdiv_rn(a.x, c);
    tex[1] = __fdiv_rn(a.y, c);
    tex[2] = __fdiv_rn(a.z, c);

    float* tw = out + (size_t)NPIX * 3 + (size_t)idx * 3;
    tw[0] = wsum;
    tw[1] = wsum;
    tw[2] = wsum;
}

extern "C" void kernel_launch(void* const* d_in, const int* in_sizes, int n_in,
                              void* d_out, int out_size) {
    const int*   p2f    = (const int*)  d_in[0];
    const float* bary   = (const float*)d_in[1];
    const float* dists  = (const float*)d_in[2];
    const float* zbuf   = (const float*)d_in[3];
    const float* images = (const float*)d_in[4];
    const float* fuv    = (const float*)d_in[5];
    float* out = (float*)d_out;

    const int threads = 256;
    const int blocks = (NPIX + threads - 1) / threads;

    zero_accum_kernel<<<blocks, threads>>>();
    splat_kernel<<<blocks, threads>>>(p2f, bary, dists, zbuf, images, fuv);
    finalize_kernel<<<blocks, threads>>>(out);
}